// round 1
// baseline (speedup 1.0000x reference)
#include <cuda_runtime.h>
#include <math.h>
#include <stdint.h>

// Problem constants (fixed by dataset)
#define Bb 4
#define Nn 1024
#define Dd 1024
#define Tt 4
#define Ee 4
#define Mm (Bb * Nn)  // 4096

// ---------------- scratch (device globals; no allocation allowed) ----------
__device__ float g_xctx[Bb * Nn * Dd];
__device__ float g_xc[Bb * Nn * Dd];
__device__ float g_plpc[Bb * Nn * Dd];
__device__ float g_q[Bb * Nn * Dd];
__device__ float g_k[Bb * Nn * Dd];
__device__ float g_v[Bb * Nn * Dd];
__device__ float g_prob[Bb * Nn * Nn];
__device__ float g_msg[Bb * Nn * Dd];
__device__ float g_qs[Ee * Mm];
__device__ float g_ks[Ee * Mm];
__device__ float g_qbase[Bb * Dd];
__device__ float g_cmd[Bb * Dd];
__device__ float g_pk[Bb * Dd];
__device__ float g_pv[Bb * Dd];

// ---------------- GEMM config ----------------
#define BM 128
#define BN 128
#define BKs 8

#define EPI_STORE 0
#define EPI_ADD 1
#define EPI_BIAS 2
#define EPI_BIAS_ADD 3
#define EPI_BIAS_ADD_SCALE 4
#define EPI_BIAS_MUL 5

// C[M, Dd] (+)= A[M,K](lda) @ W[N,K](ldw)^T  with epilogue variants.
// M = Mm, N = Dd, K = 1024 here; all divisible by tile sizes.
template <int EPI>
__global__ __launch_bounds__(256, 2) void gemm_nt(
    const float* __restrict__ A, int lda,
    const float* __restrict__ W, int ldw,
    float* __restrict__ C,
    const float* __restrict__ bias,
    const float* __restrict__ scale,  // [Bb, Dd], row b = m / Nn
    int K) {
  __shared__ float As[BKs][BM];
  __shared__ float Ws[BKs][BN];
  const int bm = blockIdx.y * BM;
  const int bn = blockIdx.x * BN;
  const int tid = threadIdx.x;
  const int lrow = tid >> 1;
  const int lk = (tid & 1) << 2;
  const float* Ag = A + (size_t)(bm + lrow) * lda + lk;
  const float* Wg = W + (size_t)(bn + lrow) * ldw + lk;

  float acc[8][8];
#pragma unroll
  for (int i = 0; i < 8; i++)
#pragma unroll
    for (int j = 0; j < 8; j++) acc[i][j] = 0.f;

  const int ty = tid >> 4;
  const int tx = tid & 15;

  for (int k0 = 0; k0 < K; k0 += BKs) {
    float4 av = *reinterpret_cast<const float4*>(Ag + k0);
    float4 wv = *reinterpret_cast<const float4*>(Wg + k0);
    As[lk + 0][lrow] = av.x;
    As[lk + 1][lrow] = av.y;
    As[lk + 2][lrow] = av.z;
    As[lk + 3][lrow] = av.w;
    Ws[lk + 0][lrow] = wv.x;
    Ws[lk + 1][lrow] = wv.y;
    Ws[lk + 2][lrow] = wv.z;
    Ws[lk + 3][lrow] = wv.w;
    __syncthreads();
#pragma unroll
    for (int kk = 0; kk < BKs; kk++) {
      float ar[8], wr[8];
#pragma unroll
      for (int i = 0; i < 8; i++) ar[i] = As[kk][ty * 8 + i];
#pragma unroll
      for (int j = 0; j < 8; j++) wr[j] = Ws[kk][tx * 8 + j];
#pragma unroll
      for (int i = 0; i < 8; i++)
#pragma unroll
        for (int j = 0; j < 8; j++) acc[i][j] = fmaf(ar[i], wr[j], acc[i][j]);
    }
    __syncthreads();
  }

#pragma unroll
  for (int i = 0; i < 8; i++) {
    int m = bm + ty * 8 + i;
    float* Cr = C + (size_t)m * Dd + bn + tx * 8;
    const float* sc =
        (EPI == EPI_BIAS_ADD_SCALE) ? (scale + (size_t)(m / Nn) * Dd + bn + tx * 8) : nullptr;
#pragma unroll
    for (int j = 0; j < 8; j++) {
      int n = bn + tx * 8 + j;
      float r = acc[i][j];
      if (EPI == EPI_STORE)
        Cr[j] = r;
      else if (EPI == EPI_ADD)
        Cr[j] += r;
      else if (EPI == EPI_BIAS)
        Cr[j] = r + bias[n];
      else if (EPI == EPI_BIAS_ADD)
        Cr[j] = Cr[j] + r + bias[n];
      else if (EPI == EPI_BIAS_ADD_SCALE)
        Cr[j] = (Cr[j] + r + bias[n]) * sc[j];
      else if (EPI == EPI_BIAS_MUL)
        Cr[j] = (r + bias[n]) * Cr[j];
    }
  }
}

// msg[b,i,d] = sum_j prob[b,i,j] * v[b,j,d]  (block-diagonal NN GEMM)
__global__ __launch_bounds__(256, 2) void gemm_nn(
    const float* __restrict__ A,     // prob [Mm, Nn]
    const float* __restrict__ Bmat,  // v [Mm, Dd]
    float* __restrict__ C) {         // msg [Mm, Dd]
  __shared__ float As[BKs][BM];
  __shared__ float Bs[BKs][BN];
  const int bm = blockIdx.y * BM;
  const int bn = blockIdx.x * BN;
  const int tid = threadIdx.x;
  const int lrow = tid >> 1;
  const int lk = (tid & 1) << 2;
  const int brow = tid >> 5;         // 0..7
  const int bcol = (tid & 31) << 2;  // 0..124
  const int bb = bm / Nn;
  const float* Ag = A + (size_t)(bm + lrow) * Nn + lk;
  const float* Bg = Bmat + (size_t)bb * Nn * Dd + (size_t)brow * Dd + bn + bcol;

  float acc[8][8];
#pragma unroll
  for (int i = 0; i < 8; i++)
#pragma unroll
    for (int j = 0; j < 8; j++) acc[i][j] = 0.f;

  const int ty = tid >> 4;
  const int tx = tid & 15;

  for (int k0 = 0; k0 < Nn; k0 += BKs) {
    float4 av = *reinterpret_cast<const float4*>(Ag + k0);
    float4 bv = *reinterpret_cast<const float4*>(Bg + (size_t)k0 * Dd);
    As[lk + 0][lrow] = av.x;
    As[lk + 1][lrow] = av.y;
    As[lk + 2][lrow] = av.z;
    As[lk + 3][lrow] = av.w;
    *reinterpret_cast<float4*>(&Bs[brow][bcol]) = bv;
    __syncthreads();
#pragma unroll
    for (int kk = 0; kk < BKs; kk++) {
      float ar[8], br[8];
#pragma unroll
      for (int i = 0; i < 8; i++) ar[i] = As[kk][ty * 8 + i];
#pragma unroll
      for (int j = 0; j < 8; j++) br[j] = Bs[kk][tx * 8 + j];
#pragma unroll
      for (int i = 0; i < 8; i++)
#pragma unroll
        for (int j = 0; j < 8; j++) acc[i][j] = fmaf(ar[i], br[j], acc[i][j]);
    }
    __syncthreads();
  }

#pragma unroll
  for (int i = 0; i < 8; i++) {
    int m = bm + ty * 8 + i;
    float* Cr = C + (size_t)m * Dd + bn + tx * 8;
#pragma unroll
    for (int j = 0; j < 8; j++) Cr[j] = acc[i][j];
  }
}

// out[r, n] = act(dot(x[r,:], w[n,:]) + b[n]); grid (Dd/8, rows), 8 warps/block
__global__ void small_nt(const float* __restrict__ x, const float* __restrict__ w,
                         const float* __restrict__ b, float* __restrict__ out,
                         int K, int act) {
  const int lane = threadIdx.x & 31;
  const int wid = threadIdx.x >> 5;
  const int n = blockIdx.x * 8 + wid;
  const int r = blockIdx.y;
  const float* xr = x + (size_t)r * K;
  const float* wr = w + (size_t)n * K;
  float s = 0.f;
  for (int c = lane; c < K; c += 32) s = fmaf(xr[c], wr[c], s);
#pragma unroll
  for (int o = 16; o; o >>= 1) s += __shfl_down_sync(0xffffffffu, s, o);
  if (lane == 0) {
    s += b[n];
    if (act) s = s > 0.f ? s : (expf(s) - 1.f);
    out[(size_t)r * Dd + n] = s;
  }
}

// qs[a][m] = q[m,:]·wes[a,0:D]; ks[a][m] = k[m,:]·wes[a,D:2D]
__global__ __launch_bounds__(256) void qsks_kernel(
    const float* __restrict__ q, const float* __restrict__ k,
    const float* __restrict__ wes, float* __restrict__ qs, float* __restrict__ ks) {
  const int m = blockIdx.x;
  const int tid = threadIdx.x;
  float qreg[4], kreg[4];
#pragma unroll
  for (int s = 0; s < 4; s++) {
    qreg[s] = q[(size_t)m * Dd + tid + s * 256];
    kreg[s] = k[(size_t)m * Dd + tid + s * 256];
  }
  __shared__ float red[256];
  for (int a = 0; a < Ee; a++) {
    float sq = 0.f, sk = 0.f;
#pragma unroll
    for (int s = 0; s < 4; s++) {
      int c = tid + s * 256;
      sq = fmaf(qreg[s], wes[a * 2 * Dd + c], sq);
      sk = fmaf(kreg[s], wes[a * 2 * Dd + Dd + c], sk);
    }
    red[tid] = sq;
    __syncthreads();
    for (int o = 128; o; o >>= 1) {
      if (tid < o) red[tid] += red[tid + o];
      __syncthreads();
    }
    if (tid == 0) qs[a * Mm + m] = red[0];
    __syncthreads();
    red[tid] = sk;
    __syncthreads();
    for (int o = 128; o; o >>= 1) {
      if (tid < o) red[tid] += red[tid + o];
      __syncthreads();
    }
    if (tid == 0) ks[a * Mm + m] = red[0];
    __syncthreads();
  }
}

// Per-row masked leaky softmax over gathered rank-1 edge scores.
__global__ __launch_bounds__(256) void softmax_kernel(
    const int* __restrict__ adj, const int* __restrict__ types_p,
    const float* __restrict__ qs, const float* __restrict__ ks,
    float* __restrict__ prob) {
  const int m = blockIdx.x;
  const int b = m / Nn;
  const int tid = threadIdx.x;
  const int types = *types_p;
  __shared__ float qsr[Ee];
  __shared__ int enr[Ee];
  if (tid < Ee) {
    qsr[tid] = qs[tid * Mm + m];
    enr[tid] = (types >> (tid + 1)) & 1;
  }
  __syncthreads();
  float lv[4];
  float mx = -INFINITY;
#pragma unroll
  for (int s = 0; s < 4; s++) {
    int j = tid + s * 256;
    int a = adj[(size_t)m * Nn + j];
    float l;
    if (a == 0) {
      l = -9e15f;
    } else if (!enr[a - 1]) {
      l = 0.f;  // disabled type: score 0, leaky(0)=0
    } else {
      float sc = qsr[a - 1] + ks[(size_t)(a - 1) * Mm + (size_t)b * Nn + j];
      l = sc > 0.f ? sc : 0.2f * sc;
    }
    lv[s] = l;
    mx = fmaxf(mx, l);
  }
  __shared__ float red[256];
  red[tid] = mx;
  __syncthreads();
  for (int o = 128; o; o >>= 1) {
    if (tid < o) red[tid] = fmaxf(red[tid], red[tid + o]);
    __syncthreads();
  }
  mx = red[0];
  __syncthreads();
  float sum = 0.f;
#pragma unroll
  for (int s = 0; s < 4; s++) {
    lv[s] = expf(lv[s] - mx);
    sum += lv[s];
  }
  red[tid] = sum;
  __syncthreads();
  for (int o = 128; o; o >>= 1) {
    if (tid < o) red[tid] += red[tid + o];
    __syncthreads();
  }
  const float inv = 1.f / red[0];
#pragma unroll
  for (int s = 0; s < 4; s++) prob[(size_t)m * Nn + tid + s * 256] = lv[s] * inv;
}

// xctx[b,n,:] = init_mem[:]
__global__ void init_xctx(const float* __restrict__ init, float* __restrict__ xctx) {
  int i = blockIdx.x * blockDim.x + threadIdx.x;
  float4 v = *reinterpret_cast<const float4*>(init + ((i * 4) & (Dd - 1)));
  reinterpret_cast<float4*>(xctx)[i] = v;
}

// xc = xctx * mask broadcast over D
__global__ void xc_kernel(const float* __restrict__ xctx, const float* __restrict__ mask,
                          float* __restrict__ xc) {
  int i = blockIdx.x * blockDim.x + threadIdx.x;
  float mk = mask[i >> 8];  // (i*4)/Dd
  float4 v = reinterpret_cast<const float4*>(xctx)[i];
  v.x *= mk;
  v.y *= mk;
  v.z *= mk;
  v.w *= mk;
  reinterpret_cast<float4*>(xc)[i] = v;
}

extern "C" void kernel_launch(void* const* d_in, const int* in_sizes, int n_in,
                              void* d_out, int out_size) {
  const float* ents = (const float*)d_in[0];
  const float* ent_mask = (const float*)d_in[1];
  const float* q_enc = (const float*)d_in[2];
  const int* adj = (const int*)d_in[3];
  const int* types = (const int*)d_in[4];
  const float* init_mem = (const float*)d_in[5];
  const float* w_qin = (const float*)d_in[6];
  const float* b_qin = (const float*)d_in[7];
  const float* w_qt = (const float*)d_in[8];
  const float* b_qt = (const float*)d_in[9];
  const float* w_pl = (const float*)d_in[10];
  const float* b_pl = (const float*)d_in[11];
  const float* w_pc = (const float*)d_in[12];
  const float* b_pc = (const float*)d_in[13];
  const float* w_q = (const float*)d_in[14];
  const float* b_q = (const float*)d_in[15];
  const float* w_k = (const float*)d_in[16];
  const float* b_k = (const float*)d_in[17];
  const float* w_v = (const float*)d_in[18];
  const float* b_v = (const float*)d_in[19];
  const float* w_pk = (const float*)d_in[20];
  const float* b_pk = (const float*)d_in[21];
  const float* w_pv = (const float*)d_in[22];
  const float* b_pv = (const float*)d_in[23];
  const float* wes = (const float*)d_in[24];
  const float* w_mu = (const float*)d_in[25];
  const float* b_mu = (const float*)d_in[26];
  const float* w_cb = (const float*)d_in[27];
  const float* b_cb = (const float*)d_in[28];
  float* out = (float*)d_out;

  float *xctx, *xc, *plpc, *q, *k, *v, *prob, *msg, *qs, *ks, *qbase, *cmd, *pk, *pv;
  cudaGetSymbolAddress((void**)&xctx, g_xctx);
  cudaGetSymbolAddress((void**)&xc, g_xc);
  cudaGetSymbolAddress((void**)&plpc, g_plpc);
  cudaGetSymbolAddress((void**)&q, g_q);
  cudaGetSymbolAddress((void**)&k, g_k);
  cudaGetSymbolAddress((void**)&v, g_v);
  cudaGetSymbolAddress((void**)&prob, g_prob);
  cudaGetSymbolAddress((void**)&msg, g_msg);
  cudaGetSymbolAddress((void**)&qs, g_qs);
  cudaGetSymbolAddress((void**)&ks, g_ks);
  cudaGetSymbolAddress((void**)&qbase, g_qbase);
  cudaGetSymbolAddress((void**)&cmd, g_cmd);
  cudaGetSymbolAddress((void**)&pk, g_pk);
  cudaGetSymbolAddress((void**)&pv, g_pv);

  const dim3 gMain(Dd / BN, Mm / BM);  // (8, 32)
  const dim3 bMain(256);
  const dim3 gSmall(Dd / 8, Bb);
  const int ew = Bb * Nn * Dd / 4;  // float4 count

  // q_base = elu(lin(q_enc, w_qin, b_qin))
  small_nt<<<gSmall, 256>>>(q_enc, w_qin, b_qin, qbase, Dd, 1);
  // x_ctx = broadcast(init_mem)
  init_xctx<<<ew / 256, 256>>>(init_mem, xctx);

  for (int t = 0; t < Tt; t++) {
    small_nt<<<gSmall, 256>>>(qbase, w_qt + (size_t)t * Dd * Dd, b_qt + (size_t)t * Dd, cmd, Dd, 0);
    small_nt<<<gSmall, 256>>>(cmd, w_pk, b_pk, pk, Dd, 0);
    small_nt<<<gSmall, 256>>>(cmd, w_pv, b_pv, pv, Dd, 0);
    xc_kernel<<<ew / 256, 256>>>(xctx, ent_mask, xc);

    // plpc = (x_loc@w_pl^T + b_pl) * (xc@w_pc^T + b_pc)
    gemm_nt<EPI_BIAS><<<gMain, bMain>>>(ents, Dd, w_pl, Dd, plpc, b_pl, nullptr, Dd);
    gemm_nt<EPI_BIAS_MUL><<<gMain, bMain>>>(xc, Dd, w_pc, Dd, plpc, b_pc, nullptr, Dd);

    // q = x_joint @ w_q^T + b_q   (split K=3072 into 3)
    gemm_nt<EPI_STORE><<<gMain, bMain>>>(ents, Dd, w_q, 3 * Dd, q, nullptr, nullptr, Dd);
    gemm_nt<EPI_ADD><<<gMain, bMain>>>(xc, Dd, w_q + Dd, 3 * Dd, q, nullptr, nullptr, Dd);
    gemm_nt<EPI_BIAS_ADD><<<gMain, bMain>>>(plpc, Dd, w_q + 2 * Dd, 3 * Dd, q, b_q, nullptr, Dd);
    // k = (x_joint @ w_k^T + b_k) * pk[b,:]
    gemm_nt<EPI_STORE><<<gMain, bMain>>>(ents, Dd, w_k, 3 * Dd, k, nullptr, nullptr, Dd);
    gemm_nt<EPI_ADD><<<gMain, bMain>>>(xc, Dd, w_k + Dd, 3 * Dd, k, nullptr, nullptr, Dd);
    gemm_nt<EPI_BIAS_ADD_SCALE><<<gMain, bMain>>>(plpc, Dd, w_k + 2 * Dd, 3 * Dd, k, b_k, pk, Dd);
    // v = (x_joint @ w_v^T + b_v) * pv[b,:]
    gemm_nt<EPI_STORE><<<gMain, bMain>>>(ents, Dd, w_v, 3 * Dd, v, nullptr, nullptr, Dd);
    gemm_nt<EPI_ADD><<<gMain, bMain>>>(xc, Dd, w_v + Dd, 3 * Dd, v, nullptr, nullptr, Dd);
    gemm_nt<EPI_BIAS_ADD_SCALE><<<gMain, bMain>>>(plpc, Dd, w_v + 2 * Dd, 3 * Dd, v, b_v, pv, Dd);

    // rank-1 edge score tables
    qsks_kernel<<<Mm, 256>>>(q, k, wes, qs, ks);
    // masked leaky softmax -> prob
    softmax_kernel<<<Mm, 256>>>(adj, types, qs, ks, prob);
    // message = prob @ v (batched)
    gemm_nn<<<gMain, bMain>>>(prob, v, msg);

    // x_ctx = [xc, message] @ w_mu^T + b_mu
    gemm_nt<EPI_STORE><<<gMain, bMain>>>(xc, Dd, w_mu, 2 * Dd, xctx, nullptr, nullptr, Dd);
    gemm_nt<EPI_BIAS_ADD><<<gMain, bMain>>>(msg, Dd, w_mu + Dd, 2 * Dd, xctx, b_mu, nullptr, Dd);
  }

  // out = [x_loc, x_ctx] @ w_cb^T + b_cb
  gemm_nt<EPI_STORE><<<gMain, bMain>>>(ents, Dd, w_cb, 2 * Dd, out, nullptr, nullptr, Dd);
  gemm_nt<EPI_BIAS_ADD><<<gMain, bMain>>>(xctx, Dd, w_cb + Dd, 2 * Dd, out, b_cb, nullptr, Dd);
}